// round 8
// baseline (speedup 1.0000x reference)
#include <cuda_runtime.h>
#include <cuda_bf16.h>
#include <mma.h>
#include <cstddef>

using namespace nvcuda;

#define Bc 4
#define Sc 1024
#define Dc 1024
#define Hc 16
#define DKc 64
#define DVc 64
#define Mc (Bc * Sc)
#define HDc (Hc * DKc)
#define QP_ELEMS (Mc * HDc)

// ---------------- Static device scratch ----------------
__device__ __nv_bfloat16 g_Qph[QP_ELEMS], g_Qpl[QP_ELEMS];   // [B,H,S,64] hi/lo
__device__ __nv_bfloat16 g_Kph[QP_ELEMS], g_Kpl[QP_ELEMS];
__device__ __nv_bfloat16 g_Vp[QP_ELEMS];                     // [B,H,S,64]
__device__ __nv_bfloat16 g_ctx[Mc * HDc];                    // [B,S,1024]
__device__ __nv_bfloat16 g_attn_bf[(size_t)Bc * Hc * Sc * Sc]; // bf16 probs
__device__ float g_obuf[Mc * Dc];
__device__ float g_attn_fb[(size_t)Bc * Hc * Sc * Sc];
__device__ int   g_mask_mode;

using bfrag_a  = wmma::fragment<wmma::matrix_a, 16, 16, 16, __nv_bfloat16, wmma::row_major>;
using bfrag_b  = wmma::fragment<wmma::matrix_b, 16, 16, 16, __nv_bfloat16, wmma::row_major>;
using bfrag_bc = wmma::fragment<wmma::matrix_b, 16, 16, 16, __nv_bfloat16, wmma::col_major>;
using bfrag_c  = wmma::fragment<wmma::accumulator, 16, 16, 16, float>;

__device__ __forceinline__ void cvt_store4(__nv_bfloat16* dh, __nv_bfloat16* dl, float4 v) {
    float a[4] = {v.x, v.y, v.z, v.w};
#pragma unroll
    for (int j = 0; j < 4; j++) {
        __nv_bfloat16 h = __float2bfloat16(a[j]);
        dh[j] = h;
        dl[j] = __float2bfloat16(a[j] - __bfloat162float(h));
    }
}

__device__ __forceinline__ void cvt_store4_s(__nv_bfloat16* dh, float4 v) {
    dh[0] = __float2bfloat16(v.x);
    dh[1] = __float2bfloat16(v.y);
    dh[2] = __float2bfloat16(v.z);
    dh[3] = __float2bfloat16(v.w);
}

__device__ __forceinline__ void cp_async16(void* smem, const void* gmem) {
    unsigned saddr = (unsigned)__cvta_generic_to_shared(smem);
    asm volatile("cp.async.cg.shared.global [%0], [%1], 16;\n" :: "r"(saddr), "l"(gmem));
}
__device__ __forceinline__ void cp_async_commit() {
    asm volatile("cp.async.commit_group;\n" ::: "memory");
}
template <int N>
__device__ __forceinline__ void cp_async_wait() {
    asm volatile("cp.async.wait_group %0;\n" :: "n"(N) : "memory");
}

// ---------------------------------------------------------------------------
__global__ void detect_mask_kernel(const unsigned int* __restrict__ m) {
    bool allint = true, allfloat = true;
    for (int i = 0; i < 1024; i++) {
        unsigned int w = m[i];
        if (w > 1u) allint = false;
        if (w != 0u && w != 0x3F800000u) allfloat = false;
    }
    g_mask_mode = allint ? 0 : (allfloat ? 2 : 1);
}

// ---------------------------------------------------------------------------
// Merged QKV projection: grid z = 0(Q,split), 1(K,split), 2(V,single).
// BM=128, BN=128, BK=16, warp tile 32x64, double-buffered smem.
// ---------------------------------------------------------------------------
__global__ __launch_bounds__(256)
void qkv_proj(const float* __restrict__ q, const float* __restrict__ k,
              const float* __restrict__ v,
              const float* __restrict__ Wq, const float* __restrict__ Wk,
              const float* __restrict__ Wv,
              const float* __restrict__ bq, const float* __restrict__ bk,
              const float* __restrict__ bv,
              __nv_bfloat16* __restrict__ Qph, __nv_bfloat16* __restrict__ Qpl,
              __nv_bfloat16* __restrict__ Kph, __nv_bfloat16* __restrict__ Kpl,
              __nv_bfloat16* __restrict__ Vp) {
    constexpr int LDA = 24;
    constexpr int LDW = 136;
    constexpr int LDST = 132;

    __shared__ __align__(16) char buf[41984];
    __nv_bfloat16* Ahi = (__nv_bfloat16*)buf;        // [2][128][24]
    __nv_bfloat16* Alo = Ahi + 2 * 128 * LDA;
    __nv_bfloat16* Whi = Alo + 2 * 128 * LDA;        // [2][16][136]
    __nv_bfloat16* Wlo = Whi + 2 * 16 * LDW;
    float* stg = (float*)buf;

    const int z = blockIdx.z;
    const bool SPLIT = (z < 2);
    const float* A    = (z == 0) ? q  : (z == 1) ? k  : v;
    const float* W    = (z == 0) ? Wq : (z == 1) ? Wk : Wv;
    const float* bias = (z == 0) ? bq : (z == 1) ? bk : bv;
    __nv_bfloat16* Ch = (z == 0) ? Qph : Kph;
    __nv_bfloat16* Cl = (z == 0) ? Qpl : Kpl;

    const int tid = threadIdx.x;
    const int w = tid >> 5;
    const int wm = w >> 1;
    const int wn = w & 1;
    const int row0 = blockIdx.y * 128;
    const int col0 = blockIdx.x * 128;

    const int ar = tid >> 2, ac = (tid & 3) * 4;
    const int wr0 = tid >> 5, wc0 = (tid & 31) * 4;

    bfrag_c acc[2][4];
#pragma unroll
    for (int ti = 0; ti < 2; ti++)
#pragma unroll
        for (int tj = 0; tj < 4; tj++) wmma::fill_fragment(acc[ti][tj], 0.0f);

    float4 ra0, ra1, rw0, rw1;
    ra0 = *(const float4*)&A[(size_t)(row0 + ar) * Dc + ac];
    ra1 = *(const float4*)&A[(size_t)(row0 + ar + 64) * Dc + ac];
    rw0 = *(const float4*)&W[(size_t)wr0 * HDc + col0 + wc0];
    rw1 = *(const float4*)&W[(size_t)(wr0 + 8) * HDc + col0 + wc0];
    if (SPLIT) {
        cvt_store4(Ahi + ar * LDA + ac, Alo + ar * LDA + ac, ra0);
        cvt_store4(Ahi + (ar + 64) * LDA + ac, Alo + (ar + 64) * LDA + ac, ra1);
        cvt_store4(Whi + wr0 * LDW + wc0, Wlo + wr0 * LDW + wc0, rw0);
        cvt_store4(Whi + (wr0 + 8) * LDW + wc0, Wlo + (wr0 + 8) * LDW + wc0, rw1);
    } else {
        cvt_store4_s(Ahi + ar * LDA + ac, ra0);
        cvt_store4_s(Ahi + (ar + 64) * LDA + ac, ra1);
        cvt_store4_s(Whi + wr0 * LDW + wc0, rw0);
        cvt_store4_s(Whi + (wr0 + 8) * LDW + wc0, rw1);
    }
    __syncthreads();

    for (int kt = 0; kt < 64; kt++) {
        if (kt < 63) {
            int kk = (kt + 1) * 16;
            ra0 = *(const float4*)&A[(size_t)(row0 + ar) * Dc + kk + ac];
            ra1 = *(const float4*)&A[(size_t)(row0 + ar + 64) * Dc + kk + ac];
            rw0 = *(const float4*)&W[(size_t)(kk + wr0) * HDc + col0 + wc0];
            rw1 = *(const float4*)&W[(size_t)(kk + wr0 + 8) * HDc + col0 + wc0];
        }
        const int cur = kt & 1;
        const int cb = cur * 128 * LDA;
        const int wb = cur * 16 * LDW;

        bfrag_a fah[2], fal[2];
#pragma unroll
        for (int ti = 0; ti < 2; ti++) {
            wmma::load_matrix_sync(fah[ti], Ahi + cb + (wm * 32 + ti * 16) * LDA, LDA);
            if (SPLIT)
                wmma::load_matrix_sync(fal[ti], Alo + cb + (wm * 32 + ti * 16) * LDA, LDA);
        }
#pragma unroll
        for (int tj = 0; tj < 4; tj++) {
            bfrag_b fbh, fbl;
            wmma::load_matrix_sync(fbh, Whi + wb + wn * 64 + tj * 16, LDW);
            if (SPLIT) wmma::load_matrix_sync(fbl, Wlo + wb + wn * 64 + tj * 16, LDW);
#pragma unroll
            for (int ti = 0; ti < 2; ti++) {
                wmma::mma_sync(acc[ti][tj], fah[ti], fbh, acc[ti][tj]);
                if (SPLIT) {
                    wmma::mma_sync(acc[ti][tj], fah[ti], fbl, acc[ti][tj]);
                    wmma::mma_sync(acc[ti][tj], fal[ti], fbh, acc[ti][tj]);
                }
            }
        }

        if (kt < 63) {
            const int nb = (cur ^ 1) * 128 * LDA;
            const int nw = (cur ^ 1) * 16 * LDW;
            if (SPLIT) {
                cvt_store4(Ahi + nb + ar * LDA + ac, Alo + nb + ar * LDA + ac, ra0);
                cvt_store4(Ahi + nb + (ar + 64) * LDA + ac, Alo + nb + (ar + 64) * LDA + ac, ra1);
                cvt_store4(Whi + nw + wr0 * LDW + wc0, Wlo + nw + wr0 * LDW + wc0, rw0);
                cvt_store4(Whi + nw + (wr0 + 8) * LDW + wc0, Wlo + nw + (wr0 + 8) * LDW + wc0, rw1);
            } else {
                cvt_store4_s(Ahi + nb + ar * LDA + ac, ra0);
                cvt_store4_s(Ahi + nb + (ar + 64) * LDA + ac, ra1);
                cvt_store4_s(Whi + nw + wr0 * LDW + wc0, rw0);
                cvt_store4_s(Whi + nw + (wr0 + 8) * LDW + wc0, rw1);
            }
        }
        __syncthreads();
    }

#pragma unroll
    for (int ph = 0; ph < 2; ph++) {
        if ((wm >> 1) == ph) {
#pragma unroll
            for (int ti = 0; ti < 2; ti++)
#pragma unroll
                for (int tj = 0; tj < 4; tj++)
                    wmma::store_matrix_sync(&stg[((wm & 1) * 32 + ti * 16) * LDST + wn * 64 + tj * 16],
                                            acc[ti][tj], LDST, wmma::mem_row_major);
        }
        __syncthreads();
#pragma unroll
        for (int i = tid; i < 2048; i += 256) {
            int r = i >> 5, c4 = (i & 31) * 4;
            int m = row0 + ph * 64 + r;
            int col = col0 + c4;
            float4 vv = *(float4*)&stg[r * LDST + c4];
            float4 bi = *(const float4*)&bias[col];
            vv.x += bi.x; vv.y += bi.y; vv.z += bi.z; vv.w += bi.w;
            int b = m >> 10, s = m & 1023, h = col >> 6, d = col & 63;
            size_t o = (((size_t)b * Hc + h) * Sc + s) * 64 + d;
            if (SPLIT) cvt_store4(Ch + o, Cl + o, vv);
            else       cvt_store4_s(Vp + o, vv);
        }
        __syncthreads();
    }
}

// ---------------------------------------------------------------------------
// Fused scores + mask + softmax.
// Block = 32 q-rows of one (b,h), full K=1024. 8 warps; warp owns a 16-col
// strip of each 128-col K tile. Q fragments hoisted to registers; K tiles
// double-buffered via cp.async. Softmax per warp-row, writes fp32 + bf16 probs.
// ---------------------------------------------------------------------------
#define LDS_F 1032
#define LDQ_F 72
#define FATTN_SMEM (32 * LDS_F * 4 + 2 * 32 * LDQ_F * 2 + 4 * 128 * LDQ_F * 2)

__global__ __launch_bounds__(256)
void fused_attn(const __nv_bfloat16* __restrict__ Qh, const __nv_bfloat16* __restrict__ Ql,
                const __nv_bfloat16* __restrict__ Kh, const __nv_bfloat16* __restrict__ Kl,
                const void* __restrict__ mask, float* __restrict__ attn,
                __nv_bfloat16* __restrict__ attn_bf) {
    extern __shared__ __align__(16) char dbuf[];
    float* Sbuf = (float*)dbuf;                                  // [32][1032]
    __nv_bfloat16* Qhi = (__nv_bfloat16*)(dbuf + 32 * LDS_F * 4);
    __nv_bfloat16* Qlo = Qhi + 32 * LDQ_F;
    __nv_bfloat16* Khi = Qlo + 32 * LDQ_F;                       // [2][128][72]
    __nv_bfloat16* Klo = Khi + 2 * 128 * LDQ_F;

    const int z = blockIdx.y;
    const int b = z >> 4;
    const int q0 = blockIdx.x * 32;
    const int tid = threadIdx.x;
    const int w = tid >> 5;
    const int lane = tid & 31;

    const __nv_bfloat16* Qbh = Qh + (size_t)z * Sc * 64;
    const __nv_bfloat16* Qbl = Ql + (size_t)z * Sc * 64;
    const __nv_bfloat16* Kbh = Kh + (size_t)z * Sc * 64;
    const __nv_bfloat16* Kbl = Kl + (size_t)z * Sc * 64;

    // K tile loaders: 128 rows x 64 cols bf16 per plane. 2 threads/row, 64B each.
    const int krow = tid >> 1;
    const int koff = (tid & 1) * 32;   // bf16 elems

    // Prologue: Q tile loads + K tile 0 via cp.async
    {
        int r = tid >> 3, c = (tid & 7) * 8;
        *(uint4*)&Qhi[r * LDQ_F + c] = *(const uint4*)&Qbh[(size_t)(q0 + r) * 64 + c];
        *(uint4*)&Qlo[r * LDQ_F + c] = *(const uint4*)&Qbl[(size_t)(q0 + r) * 64 + c];
    }
#pragma unroll
    for (int j = 0; j < 4; j++) {
        cp_async16(&Khi[krow * LDQ_F + koff + j * 8], &Kbh[(size_t)krow * 64 + koff + j * 8]);
        cp_async16(&Klo[krow * LDQ_F + koff + j * 8], &Kbl[(size_t)krow * 64 + koff + j * 8]);
    }
    cp_async_commit();
    cp_async_wait<0>();
    __syncthreads();

    // Hoist Q fragments (16 frags: ti x ks x hi/lo)
    bfrag_a qf_h[2][4], qf_l[2][4];
#pragma unroll
    for (int ti = 0; ti < 2; ti++)
#pragma unroll
        for (int ks = 0; ks < 4; ks++) {
            wmma::load_matrix_sync(qf_h[ti][ks], Qhi + (ti * 16) * LDQ_F + ks * 16, LDQ_F);
            wmma::load_matrix_sync(qf_l[ti][ks], Qlo + (ti * 16) * LDQ_F + ks * 16, LDQ_F);
        }

    for (int kt = 0; kt < 8; kt++) {
        if (kt < 7) {
            const int nb = ((kt + 1) & 1) * 128 * LDQ_F;
            const size_t gb = (size_t)(kt + 1) * 128 * 64;
#pragma unroll
            for (int j = 0; j < 4; j++) {
                cp_async16(&Khi[nb + krow * LDQ_F + koff + j * 8],
                           &Kbh[gb + (size_t)krow * 64 + koff + j * 8]);
                cp_async16(&Klo[nb + krow * LDQ_F + koff + j * 8],
                           &Kbl[gb + (size_t)krow * 64 + koff + j * 8]);
            }
            cp_async_commit();
            cp_async_wait<1>();
        } else {
            cp_async_wait<0>();
        }
        __syncthreads();

        const int cur = (kt & 1) * 128 * LDQ_F;
        bfrag_c acc[2];
        wmma::fill_fragment(acc[0], 0.0f);
        wmma::fill_fragment(acc[1], 0.0f);
#pragma unroll
        for (int ks = 0; ks < 4; ks++) {
            bfrag_bc fbh, fbl;
            wmma::load_matrix_sync(fbh, Khi + cur + (w * 16) * LDQ_F + ks * 16, LDQ_F);
            wmma::load_matrix_sync(fbl, Klo + cur + (w * 16) * LDQ_F + ks * 16, LDQ_F);
#pragma unroll
            for (int ti = 0; ti < 2; ti++) {
                wmma::mma_sync(acc[ti], qf_h[ti][ks], fbh, acc[ti]);
                wmma::mma_sync(acc[ti], qf_h[ti][ks], fbl, acc[ti]);
                wmma::mma_sync(acc[ti], qf_l[ti][ks], fbh, acc[ti]);
            }
        }
#pragma unroll
        for (int ti = 0; ti < 2; ti++)
            wmma::store_matrix_sync(&Sbuf[(ti * 16) * LDS_F + kt * 128 + w * 16], acc[ti],
                                    LDS_F, wmma::mem_row_major);
        __syncthreads();
    }

    // ---- softmax phase: warp w owns rows [w*4, w*4+4) ----
    const int mode = g_mask_mode;
    const int* mi = (const int*)mask;
    const unsigned char* mb8 = (const unsigned char*)mask;
    const float* mf = (const float*)mask;

    for (int rr = 0; rr < 4; rr++) {
        const int r = w * 4 + rr;
        const int qrow = q0 + r;
        float* Srow = Sbuf + r * LDS_F;
        const size_t mrow = (size_t)b * Sc * Sc + (size_t)qrow * Sc;

        float mx = -3.0e38f;
#pragma unroll
        for (int i = 0; i < 32; i++) {
            int kk = lane + i * 32;
            bool masked;
            if (mode == 0)      masked = (mi[mrow + kk] != 0);
            else if (mode == 2) masked = (mf[mrow + kk] != 0.0f);
            else                masked = (mb8[mrow + kk] != 0);
            float vv = masked ? -1e9f : Srow[kk] * 0.125f;
            Srow[kk] = vv;
            mx = fmaxf(mx, vv);
        }
#pragma unroll
        for (int o = 16; o; o >>= 1) mx = fmaxf(mx, __shfl_xor_sync(0xffffffffu, mx, o));

        float sum = 0.0f;
#pragma unroll
        for (int i = 0; i < 32; i++) {
            int kk = lane + i * 32;
            float e = expf(Srow[kk] - mx);
            Srow[kk] = e;
            sum += e;
        }
#pragma unroll
        for (int o = 16; o; o >>= 1) sum += __shfl_xor_sync(0xffffffffu, sum, o);
        float inv = 1.0f / sum;

        float4* dst = (float4*)(attn + ((size_t)z * Sc + qrow) * Sc);
        __nv_bfloat16* dstb = attn_bf + ((size_t)z * Sc + qrow) * Sc;
#pragma unroll
        for (int i = 0; i < 8; i++) {
            int k4 = lane + i * 32;
            float4 vv = *(float4*)&Srow[k4 * 4];
            vv.x *= inv; vv.y *= inv; vv.z *= inv; vv.w *= inv;
            dst[k4] = vv;
            cvt_store4_s(dstb + k4 * 4, vv);
        }
    }
}

// ---------------------------------------------------------------------------
// Context: BM=256, BN=64, single bf16, A = bf16 probs, warp tile 32x64.
// ---------------------------------------------------------------------------
__global__ __launch_bounds__(256)
void context_wide(const __nv_bfloat16* __restrict__ P, const __nv_bfloat16* __restrict__ Vp,
                  __nv_bfloat16* __restrict__ C) {
    constexpr int LDA = 24;
    constexpr int LDW = 72;
    constexpr int LDST = 68;

    __shared__ __align__(16) char buf[34816];
    __nv_bfloat16* As = (__nv_bfloat16*)buf;
    __nv_bfloat16* Ws = As + 2 * 256 * LDA;
    float* stg = (float*)buf;

    const int tid = threadIdx.x;
    const int w = tid >> 5;
    const int z = blockIdx.y;
    const int row0 = blockIdx.x * 256;

    const __nv_bfloat16* Pb = P + (size_t)z * Sc * Sc;
    const __nv_bfloat16* Vb = Vp + (size_t)z * Sc * 64;

    const int ar = tid >> 1, ac = (tid & 1) * 8;
    const int in_b = tid < 128;
    const int wr = tid >> 3, wc = (tid & 7) * 8;

    bfrag_c acc[2][4];
#pragma unroll
    for (int ti = 0; ti < 2; ti++)
#pragma unroll
        for (int tj = 0; tj < 4; tj++) wmma::fill_fragment(acc[ti][tj], 0.0f);

    uint4 pa0, pa1, pb;
    pa0 = *(const uint4*)&Pb[(size_t)(row0 + ar) * Sc + ac];
    pa1 = *(const uint4*)&Pb[(size_t)(row0 + ar + 128) * Sc + ac];
    if (in_b) pb = *(const uint4*)&Vb[(size_t)wr * 64 + wc];
    *(uint4*)&As[ar * LDA + ac] = pa0;
    *(uint4*)&As[(ar + 128) * LDA + ac] = pa1;
    if (in_b) *(uint4*)&Ws[wr * LDW + wc] = pb;
    __syncthreads();

    for (int kt = 0; kt < 64; kt++) {
        if (kt < 63) {
            int kk = (kt + 1) * 16;
            pa0 = *(const uint4*)&Pb[(size_t)(row0 + ar) * Sc + kk + ac];
            pa1 = *(const uint4*)&Pb[(size_t)(row0 + ar + 128) * Sc + kk + ac];
            if (in_b) pb = *(const uint4*)&Vb[(size_t)(kk + wr) * 64 + wc];
        }
        const int cur = kt & 1;
        const int cb = cur * 256 * LDA;
        const int wb = cur * 16 * LDW;

        bfrag_a fa[2];
#pragma unroll
        for (int ti = 0; ti < 2; ti++)
            wmma::load_matrix_sync(fa[ti], As + cb + (w * 32 + ti * 16) * LDA, LDA);
#pragma unroll
        for (int tj = 0; tj < 4; tj++) {
            bfrag_b fb;
            wmma::load_matrix_sync(fb, Ws + wb + tj * 16, LDW);
#pragma unroll
            for (int ti = 0; ti < 2; ti++)
                wmma::mma_sync(acc[ti][tj], fa[ti], fb, acc[ti][tj]);
        }

        if (kt < 63) {
            const int nb = (cur ^ 1) * 256 * LDA;
            const int nw = (cur ^ 1) * 16 * LDW;
            *(uint4*)&As[nb + ar * LDA + ac] = pa0;
            *(uint4*)&As[nb + (ar + 128) * LDA + ac] = pa1;
            if (in_b) *(uint4*)&Ws[nw + wr * LDW + wc] = pb;
        }
        __syncthreads();
    }

    const int b = z >> 4, h = z & 15;
#pragma unroll
    for (int ph = 0; ph < 2; ph++) {
        if ((w >> 2) == ph) {
#pragma unroll
            for (int ti = 0; ti < 2; ti++)
#pragma unroll
                for (int tj = 0; tj < 4; tj++)
                    wmma::store_matrix_sync(&stg[((w & 3) * 32 + ti * 16) * LDST + tj * 16],
                                            acc[ti][tj], LDST, wmma::mem_row_major);
        }
        __syncthreads();
#pragma unroll
        for (int i = tid; i < 2048; i += 256) {
            int r = i >> 4, c4 = (i & 15) * 4;
            int s = row0 + ph * 128 + r;
            float4 vv = *(float4*)&stg[r * LDST + c4];
            cvt_store4_s(C + ((size_t)(b * Sc + s)) * HDc + h * DVc + c4, vv);
        }
        __syncthreads();
    }
}

// ---------------------------------------------------------------------------
// Out-proj: BM=128, BN=128, single bf16, A = ctx bf16 plane, fp32 out.
// ---------------------------------------------------------------------------
__global__ __launch_bounds__(256)
void outproj_wide(const __nv_bfloat16* __restrict__ Ab, const float* __restrict__ W,
                  const float* __restrict__ bias, float* __restrict__ Cf) {
    constexpr int LDA = 24;
    constexpr int LDW = 136;
    constexpr int LDST = 132;

    __shared__ __align__(16) char buf[33792];
    __nv_bfloat16* As = (__nv_bfloat16*)buf;
    __nv_bfloat16* Ws = As + 2 * 128 * LDA;
    float* stg = (float*)buf;

    const int tid = threadIdx.x;
    const int w = tid >> 5;
    const int wm = w >> 1;
    const int wn = w & 1;
    const int row0 = blockIdx.y * 128;
    const int col0 = blockIdx.x * 128;

    const int br = tid >> 1, bc = (tid & 1) * 8;
    const int wr0 = tid >> 5, wc0 = (tid & 31) * 4;

    bfrag_c acc[2][4];
#pragma unroll
    for (int ti = 0; ti < 2; ti++)
#pragma unroll
        for (int tj = 0; tj < 4; tj++) wmma::fill_fragment(acc[ti][tj], 0.0f);

    uint4 pa;
    float4 rw0, rw1;
    pa = *(const uint4*)&Ab[(size_t)(row0 + br) * Dc + bc];
    rw0 = *(const float4*)&W[(size_t)wr0 * Dc + col0 + wc0];
    rw1 = *(const float4*)&W[(size_t)(wr0 + 8) * Dc + col0 + wc0];
    *(uint4*)&As[br * LDA + bc] = pa;
    cvt_store4_s(Ws + wr0 * LDW + wc0, rw0);
    cvt_store4_s(Ws + (wr0 + 8) * LDW + wc0, rw1);
    __syncthreads();

    for (int kt = 0; kt < 64; kt++) {
        if (kt < 63) {
            int kk = (kt + 1) * 16;
            pa = *(const uint4*)&Ab[(size_t)(row0 + br) * Dc + kk + bc];
            rw0 = *(const float4*)&W[(size_t)(kk + wr0) * Dc + col0 + wc0];
            rw1 = *(const float4*)&W[(size_t)(kk + wr0 + 8) * Dc + col0 + wc0];
        }
        const int cur = kt & 1;
        const int cb = cur * 128 * LDA;
        const int wb = cur * 16 * LDW;

        bfrag_a fa[2];
#pragma unroll
        for (int ti = 0; ti < 2; ti++)
            wmma::load_matrix_sync(fa[ti], As + cb + (wm * 32 + ti * 16) * LDA, LDA);
#pragma unroll
        for (int tj = 0; tj < 4; tj++) {
            bfrag_b fb;
            wmma::load_matrix_sync(fb, Ws + wb + wn * 64 + tj * 16, LDW);
#pragma unroll
            for (int ti = 0; ti < 2; ti++)
                wmma::mma_sync(acc[ti][tj], fa[ti], fb, acc[ti][tj]);
        }

        if (kt < 63) {
            const int nb = (cur ^ 1) * 128 * LDA;
            const int nw = (cur ^ 1) * 16 * LDW;
            *(uint4*)&As[nb + br * LDA + bc] = pa;
            cvt_store4_s(Ws + nw + wr0 * LDW + wc0, rw0);
            cvt_store4_s(Ws + nw + (wr0 + 8) * LDW + wc0, rw1);
        }
        __syncthreads();
    }

#pragma unroll
    for (int ph = 0; ph < 2; ph++) {
        if ((wm >> 1) == ph) {
#pragma unroll
            for (int ti = 0; ti < 2; ti++)
#pragma unroll
                for (int tj = 0; tj < 4; tj++)
                    wmma::store_matrix_sync(&stg[((wm & 1) * 32 + ti * 16) * LDST + wn * 64 + tj * 16],
                                            acc[ti][tj], LDST, wmma::mem_row_major);
        }
        __syncthreads();
#pragma unroll
        for (int i = tid; i < 2048; i += 256) {
            int r = i >> 5, c4 = (i & 31) * 4;
            int m = row0 + ph * 64 + r;
            int col = col0 + c4;
            float4 vv = *(float4*)&stg[r * LDST + c4];
            float4 bi = *(const float4*)&bias[col];
            vv.x += bi.x; vv.y += bi.y; vv.z += bi.z; vv.w += bi.w;
            *(float4*)&Cf[(size_t)m * Dc + col] = vv;
        }
        __syncthreads();
    }
}

// ---------------------------------------------------------------------------
// Fused residual add + LayerNorm
// ---------------------------------------------------------------------------
__global__ __launch_bounds__(256)
void layernorm_kernel(const float* __restrict__ x, const float* __restrict__ resid,
                      float* __restrict__ out) {
    const size_t row = blockIdx.x;
    const float4* xr = (const float4*)(x + row * Dc);
    const float4* rr = (const float4*)(resid + row * Dc);
    float4* orow = (float4*)(out + row * Dc);
    const int tid = threadIdx.x;
    const int lane = tid & 31, wid = tid >> 5;
    __shared__ float sm[16];

    float4 a = xr[tid], b = rr[tid];
    float4 v = make_float4(a.x + b.x, a.y + b.y, a.z + b.z, a.w + b.w);
    float s = (v.x + v.y) + (v.z + v.w);
#pragma unroll
    for (int o = 16; o; o >>= 1) s += __shfl_xor_sync(0xffffffffu, s, o);
    if (lane == 0) sm[wid] = s;
    __syncthreads();
    float tot = 0.0f;
#pragma unroll
    for (int i = 0; i < 8; i++) tot += sm[i];
    float mean = tot * (1.0f / 1024.0f);

    float dx = v.x - mean, dy = v.y - mean, dz = v.z - mean, dw = v.w - mean;
    float vs = (dx * dx + dy * dy) + (dz * dz + dw * dw);
#pragma unroll
    for (int o = 16; o; o >>= 1) vs += __shfl_xor_sync(0xffffffffu, vs, o);
    if (lane == 0) sm[8 + wid] = vs;
    __syncthreads();
    float vtot = 0.0f;
#pragma unroll
    for (int i = 0; i < 8; i++) vtot += sm[8 + i];
    float inv = rsqrtf(vtot * (1.0f / 1024.0f) + 1e-5f);
    orow[tid] = make_float4(dx * inv, dy * inv, dz * inv, dw * inv);
}

// ---------------------------------------------------------------------------
// Launch
// ---------------------------------------------------------------------------
extern "C" void kernel_launch(void* const* d_in, const int* in_sizes, int n_in,
                              void* d_out, int out_size) {
    const float* q    = (const float*)d_in[0];
    const float* k    = (const float*)d_in[1];
    const float* v    = (const float*)d_in[2];
    const void*  mask = d_in[3];
    const float* Wq   = (const float*)d_in[4];
    const float* bq   = (const float*)d_in[5];
    const float* Wk   = (const float*)d_in[6];
    const float* bk   = (const float*)d_in[7];
    const float* Wv   = (const float*)d_in[8];
    const float* bv   = (const float*)d_in[9];
    const float* Wo   = (const float*)d_in[10];
    const float* bo   = (const float*)d_in[11];
    float* out = (float*)d_out;

    __nv_bfloat16 *Qph, *Qpl, *Kph, *Kpl, *Vp, *ctx, *attn_bf;
    float *obuf, *attn_fb;
    cudaGetSymbolAddress((void**)&Qph, g_Qph); cudaGetSymbolAddress((void**)&Qpl, g_Qpl);
    cudaGetSymbolAddress((void**)&Kph, g_Kph); cudaGetSymbolAddress((void**)&Kpl, g_Kpl);
    cudaGetSymbolAddress((void**)&Vp, g_Vp);
    cudaGetSymbolAddress((void**)&ctx, g_ctx);
    cudaGetSymbolAddress((void**)&attn_bf, g_attn_bf);
    cudaGetSymbolAddress((void**)&obuf, g_obuf);
    cudaGetSymbolAddress((void**)&attn_fb, g_attn_fb);

    const long long LN_ELEMS = (long long)Mc * Dc;
    const long long ATTN_ELEMS = (long long)Bc * Hc * Sc * Sc;
    float* attn = ((long long)out_size >= LN_ELEMS + ATTN_ELEMS)
                      ? (out + (size_t)LN_ELEMS)
                      : attn_fb;

    static int smem_set = 0;
    if (!smem_set) {
        cudaFuncSetAttribute(fused_attn,
                             cudaFuncAttributeMaxDynamicSharedMemorySize, FATTN_SMEM);
        smem_set = 1;
    }

    detect_mask_kernel<<<1, 1>>>((const unsigned int*)mask);

    // Merged QKV projections (z: 0=Q split, 1=K split, 2=V single)
    qkv_proj<<<dim3(8, 32, 3), 256>>>(q, k, v, Wq, Wk, Wv, bq, bk, bv,
                                      Qph, Qpl, Kph, Kpl, Vp);

    // Fused scores + mask + softmax -> fp32 probs (output) + bf16 probs
    fused_attn<<<dim3(32, Bc * Hc), 256, FATTN_SMEM>>>(Qph, Qpl, Kph, Kpl,
                                                       mask, attn, attn_bf);

    // Context (bf16 probs) -> ctx bf16 plane
    context_wide<<<dim3(4, 64), 256>>>(attn_bf, Vp, ctx);

    // Output projection
    outproj_wide<<<dim3(8, 32), 256>>>(ctx, Wo, bo, obuf);

    // Residual + LayerNorm
    layernorm_kernel<<<Mc, 256>>>(obuf, q, out);
}